// round 12
// baseline (speedup 1.0000x reference)
#include <cuda_runtime.h>
#include <cuda_bf16.h>
#include <cuda_fp16.h>
#include <math.h>
#include <stdint.h>

#define B_  4
#define S_  2048
#define D_  1024
#define M_TOT (B_ * S_)   // 8192

typedef __nv_bfloat16 bf16;
typedef __half fp16;

// ---------------- scratch (allocation-free rule: __device__ globals) ----------------
__device__ bf16  g_x0[(size_t)M_TOT * D_], g_x1[(size_t)M_TOT * D_], g_x2[(size_t)M_TOT * D_];
__device__ fp16  g_xh0[(size_t)M_TOT * D_], g_xh1[(size_t)M_TOT * D_];
__device__ bf16  g_wq0[(size_t)D_ * D_], g_wq1[(size_t)D_ * D_], g_wq2[(size_t)D_ * D_];
__device__ bf16  g_wk0[(size_t)D_ * D_], g_wk1[(size_t)D_ * D_], g_wk2[(size_t)D_ * D_];
__device__ fp16  g_wvh0[(size_t)D_ * D_], g_wvh1[(size_t)D_ * D_];
__device__ bf16  g_q0[(size_t)M_TOT * D_], g_q1[(size_t)M_TOT * D_], g_q2[(size_t)M_TOT * D_];
__device__ bf16  g_k0[(size_t)M_TOT * D_], g_k1[(size_t)M_TOT * D_], g_k2[(size_t)M_TOT * D_];
__device__ fp16  g_v0[(size_t)M_TOT * D_], g_v1[(size_t)M_TOT * D_];
__device__ fp16  g_vT0[(size_t)M_TOT * D_], g_vT1[(size_t)M_TOT * D_];   // [B][D,S]
__device__ float g_s[(size_t)B_ * S_ * S_];                              // scores fp32
__device__ fp16  g_w0[(size_t)B_ * S_ * S_], g_w1[(size_t)B_ * S_ * S_]; // softmax weights split

// ---------------- helpers ----------------
__device__ __forceinline__ uint32_t smem_u32(const void* p) {
    uint32_t a;
    asm("{ .reg .u64 t; cvta.to.shared.u64 t, %1; cvt.u32.u64 %0, t; }" : "=r"(a) : "l"(p));
    return a;
}
__device__ __forceinline__ void cp_async16(uint32_t dst, const void* src) {
    asm volatile("cp.async.cg.shared.global [%0], [%1], 16;" :: "r"(dst), "l"(src) : "memory");
}
__device__ __forceinline__ void cp_commit() { asm volatile("cp.async.commit_group;" ::: "memory"); }

__device__ __forceinline__ void ldsm_x4(uint32_t* r, uint32_t addr) {
    asm volatile("ldmatrix.sync.aligned.m8n8.x4.shared.b16 {%0,%1,%2,%3}, [%4];"
        : "=r"(r[0]), "=r"(r[1]), "=r"(r[2]), "=r"(r[3]) : "r"(addr));
}

// dtype-specific ops
template<typename T> struct Ops;
template<> struct Ops<bf16> {
    static __device__ __forceinline__ void mma(float* c, const uint32_t* a, const uint32_t* b) {
        asm volatile(
            "mma.sync.aligned.m16n8k16.row.col.f32.bf16.bf16.f32 "
            "{%0,%1,%2,%3}, {%4,%5,%6,%7}, {%8,%9}, {%0,%1,%2,%3};"
            : "+f"(c[0]), "+f"(c[1]), "+f"(c[2]), "+f"(c[3])
            : "r"(a[0]), "r"(a[1]), "r"(a[2]), "r"(a[3]), "r"(b[0]), "r"(b[1]));
    }
    static __device__ __forceinline__ bf16  cvt(float v)  { return __float2bfloat16(v); }
    static __device__ __forceinline__ float back(bf16 v)  { return __bfloat162float(v); }
};
template<> struct Ops<fp16> {
    static __device__ __forceinline__ void mma(float* c, const uint32_t* a, const uint32_t* b) {
        asm volatile(
            "mma.sync.aligned.m16n8k16.row.col.f32.f16.f16.f32 "
            "{%0,%1,%2,%3}, {%4,%5,%6,%7}, {%8,%9}, {%0,%1,%2,%3};"
            : "+f"(c[0]), "+f"(c[1]), "+f"(c[2]), "+f"(c[3])
            : "r"(a[0]), "r"(a[1]), "r"(a[2]), "r"(a[3]), "r"(b[0]), "r"(b[1]));
    }
    static __device__ __forceinline__ fp16  cvt(float v)  { return __float2half_rn(v); }
    static __device__ __forceinline__ float back(fp16 v)  { return __half2float(v); }
};

template<typename T> __device__ __forceinline__ uint32_t pack2(T a, T b) {
    uint32_t u; T* p = (T*)&u; p[0] = a; p[1] = b; return u;
}

// Swizzled tile layout: 128 logical rows x 64 B (one GBK=32 K-slice of bf16/fp16).
// Rows packed pairwise into 64 storage rows of 128 B, then SW128 XOR.
#define SWZ128(x) ((x) ^ (((x) >> 3) & 0x70))
__device__ __forceinline__ uint32_t tile_off(uint32_t row, uint32_t colb) {
    return SWZ128(((row & 63u) << 7) + ((row >> 6) << 6) + colb);
}

// ---------------- GEMM: C[M,N] = A[M,K] * B[N,K]^T with NS-way split operands ----
// terms: all (i,j), i+j <= NS-1  (NS=2: 3 terms; NS=3: 6 terms)
// mode 0: fp32 C ; mode 1: 2-way T (C0,C1) ; mode 2: 3-way T (C0,C1,C2)
// zmode 0: blockIdx.z = batch (strides sA/sB/sC)
// zmode 1: blockIdx.z selects operand/output set (0: B*/C*, 1: Bb*/Cb*)  [QK fusion]
#define GBM 128
#define GBN 128
#define GBK 32
#define TILE_BYTES 8192

template<int NS, int NSTAGE, typename T>
__global__ __launch_bounds__(256, 2) void mma_gemm(
    const T* __restrict__ A0, const T* __restrict__ A1, const T* __restrict__ A2,
    const T* B0, const T* B1, const T* B2,
    const T* B0b, const T* B1b, const T* B2b,
    float* C, T* C0, T* C1, T* C2,
    float* Cb, T* C0b, T* C1b, T* C2b,
    int M, int N, int K, long sA, long sB, long sC, int mode, int zmode)
{
    constexpr int STAGE_BYTES = 2 * NS * TILE_BYTES;
    extern __shared__ char sm[];
    const uint32_t sbase = smem_u32(sm);

    const int tid  = threadIdx.x;
    const int wid  = tid >> 5;
    const int lane = tid & 31;
    const int gid  = lane >> 2;
    const int tig  = lane & 3;

    if (zmode == 1 && blockIdx.z == 1) {
        B0 = B0b; B1 = B1b; B2 = B2b;
        C = Cb; C0 = C0b; C1 = C1b; C2 = C2b;
    }
    const long zb = (zmode == 0) ? (long)blockIdx.z : 0;

    const int by = blockIdx.y * GBM;
    const int bx = blockIdx.x * GBN;

    const T* srcs[2 * NS];
    srcs[0] = A0 + zb * sA + (long)by * K;
    srcs[1] = A1 + zb * sA + (long)by * K;
    if (NS == 3) srcs[2] = A2 + zb * sA + (long)by * K;
    srcs[NS + 0] = B0 + zb * sB + (long)bx * K;
    srcs[NS + 1] = B1 + zb * sB + (long)bx * K;
    if (NS == 3) srcs[NS + 2] = B2 + zb * sB + (long)bx * K;

    const int NT = K / GBK;

    auto load_stage = [&](int st, int kt) {
        #pragma unroll
        for (int t = 0; t < 2 * NS; t++) {
            const char* sp = (const char*)srcs[t] + kt * 64;
            uint32_t db = sbase + st * STAGE_BYTES + t * TILE_BYTES;
            #pragma unroll
            for (int p = 0; p < 2; p++) {
                int idx = p * 256 + tid;       // 0..511
                uint32_t row = idx >> 2;
                uint32_t c   = idx & 3;
                cp_async16(db + tile_off(row, c << 4), sp + (long)row * K * 2 + c * 16);
            }
        }
        cp_commit();
    };

    const int wm = (wid & 1) * 64;
    const int wn = (wid >> 1) * 32;

    float acc[4][4][4] = {};

    #pragma unroll
    for (int s = 0; s < NSTAGE - 1; s++) load_stage(s, s);

    for (int kt = 0; kt < NT; kt++) {
        asm volatile("cp.async.wait_group %0;" :: "n"(NSTAGE - 2) : "memory");
        __syncthreads();
        if (kt + NSTAGE - 1 < NT)
            load_stage((kt + NSTAGE - 1) % NSTAGE, kt + NSTAGE - 1);

        uint32_t abase = sbase + (kt % NSTAGE) * STAGE_BYTES;
        #pragma unroll
        for (int ks = 0; ks < GBK; ks += 16) {
            // B fragments upfront: ldsm x4 over n16 x k16 per split
            uint32_t b[NS][4][2];
            #pragma unroll
            for (int ntp = 0; ntp < 2; ntp++) {
                uint32_t r = wn + ntp * 16 + (lane & 15);
                uint32_t cb = ((ks >> 3) + (lane >> 4)) << 4;
                uint32_t rb = abase + NS * TILE_BYTES + tile_off(r, cb);
                #pragma unroll
                for (int s = 0; s < NS; s++) {
                    uint32_t t4[4];
                    ldsm_x4(t4, rb + s * TILE_BYTES);
                    b[s][ntp * 2 + 0][0] = t4[0]; b[s][ntp * 2 + 0][1] = t4[2];
                    b[s][ntp * 2 + 1][0] = t4[1]; b[s][ntp * 2 + 1][1] = t4[3];
                }
            }
            // A per mt, then MMAs
            #pragma unroll
            for (int mt = 0; mt < 4; mt++) {
                uint32_t a[NS][4];
                uint32_t r = wm + mt * 16 + (lane & 15);
                uint32_t cb = ((ks >> 3) + (lane >> 4)) << 4;
                uint32_t ra = abase + tile_off(r, cb);
                #pragma unroll
                for (int s = 0; s < NS; s++)
                    ldsm_x4(a[s], ra + s * TILE_BYTES);
                #pragma unroll
                for (int nt = 0; nt < 4; nt++) {
                    #pragma unroll
                    for (int i = 0; i < NS; i++)
                        #pragma unroll
                        for (int j = 0; j < NS; j++)
                            if (i + j <= NS - 1)
                                Ops<T>::mma(acc[mt][nt], a[i], b[j][nt]);
                }
            }
        }
    }

    // epilogue
    #pragma unroll
    for (int mt = 0; mt < 4; mt++) {
        #pragma unroll
        for (int nt = 0; nt < 4; nt++) {
            int col = bx + wn + nt * 8 + 2 * tig;
            #pragma unroll
            for (int h = 0; h < 2; h++) {
                int row = by + wm + mt * 16 + gid + h * 8;
                float v0 = acc[mt][nt][2 * h + 0];
                float v1 = acc[mt][nt][2 * h + 1];
                if (mode == 0) {
                    *(float2*)(C + zb * sC + (long)row * N + col) = make_float2(v0, v1);
                } else {
                    long base = (long)row * N + col;
                    T h0 = Ops<T>::cvt(v0);
                    T h1 = Ops<T>::cvt(v1);
                    float r0 = v0 - Ops<T>::back(h0);
                    float r1 = v1 - Ops<T>::back(h1);
                    T m0 = Ops<T>::cvt(r0);
                    T m1 = Ops<T>::cvt(r1);
                    *(uint32_t*)(C0 + base) = pack2<T>(h0, h1);
                    *(uint32_t*)(C1 + base) = pack2<T>(m0, m1);
                    if (mode == 2) {
                        T l0 = Ops<T>::cvt(r0 - Ops<T>::back(m0));
                        T l1 = Ops<T>::cvt(r1 - Ops<T>::back(m1));
                        *(uint32_t*)(C2 + base) = pack2<T>(l0, l1);
                    }
                }
            }
        }
    }
}

// ---------------- split x: fp32 -> 3-way bf16  AND 2-way fp16 ----------------
__global__ __launch_bounds__(256) void split_x(const float* __restrict__ in,
        bf16* __restrict__ o0, bf16* __restrict__ o1, bf16* __restrict__ o2,
        fp16* __restrict__ p0, fp16* __restrict__ p1, long n)
{
    long i = ((long)blockIdx.x * 256 + threadIdx.x) * 4;
    if (i >= n) return;
    float4 v = *(const float4*)(in + i);
    float vv[4] = {v.x, v.y, v.z, v.w};
    #pragma unroll
    for (int j = 0; j < 4; j++) {
        float x = vv[j];
        bf16 h = __float2bfloat16(x);
        float r = x - __bfloat162float(h);
        bf16 m = __float2bfloat16(r);
        bf16 l = __float2bfloat16(r - __bfloat162float(m));
        o0[i + j] = h; o1[i + j] = m; o2[i + j] = l;
        fp16 hh = __float2half_rn(x);
        fp16 hl = __float2half_rn(x - __half2float(hh));
        p0[i + j] = hh; p1[i + j] = hl;
    }
}

// ---------------- split + transpose: fp32 [K,N] -> 3-way bf16 [N,K] ----------------
__global__ __launch_bounds__(256) void splitT3_f32(const float* __restrict__ in,
        bf16* __restrict__ o0, bf16* __restrict__ o1, bf16* __restrict__ o2, int Kd, int Nd)
{
    __shared__ float t[32][33];
    int tx = threadIdx.x & 31, ty = threadIdx.x >> 5;   // 32 x 8
    int c0 = blockIdx.x * 32, r0 = blockIdx.y * 32;
    #pragma unroll
    for (int j = 0; j < 4; j++)
        t[ty + j * 8][tx] = in[(long)(r0 + ty + j * 8) * Nd + c0 + tx];
    __syncthreads();
    #pragma unroll
    for (int j = 0; j < 4; j++) {
        float v = t[tx][ty + j * 8];
        bf16 h = __float2bfloat16(v);
        float r = v - __bfloat162float(h);
        bf16 m = __float2bfloat16(r);
        bf16 l = __float2bfloat16(r - __bfloat162float(m));
        long o = (long)(c0 + ty + j * 8) * Kd + r0 + tx;
        o0[o] = h; o1[o] = m; o2[o] = l;
    }
}

// ---------------- split + transpose: fp32 [K,N] -> 2-way fp16 [N,K] ----------------
__global__ __launch_bounds__(256) void splitT2h_f32(const float* __restrict__ in,
        fp16* __restrict__ o0, fp16* __restrict__ o1, int Kd, int Nd)
{
    __shared__ float t[32][33];
    int tx = threadIdx.x & 31, ty = threadIdx.x >> 5;
    int c0 = blockIdx.x * 32, r0 = blockIdx.y * 32;
    #pragma unroll
    for (int j = 0; j < 4; j++)
        t[ty + j * 8][tx] = in[(long)(r0 + ty + j * 8) * Nd + c0 + tx];
    __syncthreads();
    #pragma unroll
    for (int j = 0; j < 4; j++) {
        float v = t[tx][ty + j * 8];
        fp16 h = __float2half_rn(v);
        fp16 l = __float2half_rn(v - __half2float(h));
        long o = (long)(c0 + ty + j * 8) * Kd + r0 + tx;
        o0[o] = h; o1[o] = l;
    }
}

// ---------------- batched fp16 transpose: [B][S,D] -> [B][D,S]  (z = batch*2 + which) --
__global__ __launch_bounds__(256) void transpose_fp16(const fp16* __restrict__ inh, const fp16* __restrict__ inl,
                                                      fp16* __restrict__ outh, fp16* __restrict__ outl)
{
    __shared__ fp16 t[32][33];
    int which = blockIdx.z & 1, b = blockIdx.z >> 1;
    const fp16* in = which ? inl : inh;
    fp16* out = which ? outl : outh;
    in  += (long)b * S_ * D_;
    out += (long)b * S_ * D_;
    int tx = threadIdx.x & 31, ty = threadIdx.x >> 5;
    int c0 = blockIdx.x * 32, r0 = blockIdx.y * 32;
    #pragma unroll
    for (int j = 0; j < 4; j++)
        t[ty + j * 8][tx] = in[(long)(r0 + ty + j * 8) * D_ + c0 + tx];
    __syncthreads();
    #pragma unroll
    for (int j = 0; j < 4; j++)
        out[(long)(c0 + ty + j * 8) * S_ + r0 + tx] = t[tx][ty + j * 8];
}

// ---------------- softmax: fp32 scores row -> 2-way fp16 weights ----------------
__global__ __launch_bounds__(256) void softmax_rows(const float* __restrict__ Sp,
                                                    fp16* __restrict__ W0, fp16* __restrict__ W1)
{
    const float* p = Sp + (long)blockIdx.x * S_;
    fp16* p0 = W0 + (long)blockIdx.x * S_;
    fp16* p1 = W1 + (long)blockIdx.x * S_;
    const int tid = threadIdx.x;
    const int PER = S_ / 256;

    float vals[PER];
    float lmax = -INFINITY;
    #pragma unroll
    for (int i = 0; i < PER; i++) {
        vals[i] = p[tid + i * 256];
        lmax = fmaxf(lmax, vals[i]);
    }
    __shared__ float red[8];
    #pragma unroll
    for (int o = 16; o; o >>= 1) lmax = fmaxf(lmax, __shfl_xor_sync(0xFFFFFFFFu, lmax, o));
    if ((tid & 31) == 0) red[tid >> 5] = lmax;
    __syncthreads();
    float m = red[0];
    #pragma unroll
    for (int w = 1; w < 8; w++) m = fmaxf(m, red[w]);
    __syncthreads();

    float lsum = 0.f;
    #pragma unroll
    for (int i = 0; i < PER; i++) { vals[i] = expf(vals[i] - m); lsum += vals[i]; }
    #pragma unroll
    for (int o = 16; o; o >>= 1) lsum += __shfl_xor_sync(0xFFFFFFFFu, lsum, o);
    if ((tid & 31) == 0) red[tid >> 5] = lsum;
    __syncthreads();
    float s = 0.f;
    #pragma unroll
    for (int w = 0; w < 8; w++) s += red[w];
    float inv = 1.0f / s;
    #pragma unroll
    for (int i = 0; i < PER; i++) {
        float w = vals[i] * inv;
        fp16 h = __float2half_rn(w);
        fp16 l = __float2half_rn(w - __half2float(h));
        p0[tid + i * 256] = h;
        p1[tid + i * 256] = l;
    }
}

// ---------------- launch ----------------
extern "C" void kernel_launch(void* const* d_in, const int* in_sizes, int n_in,
                              void* d_out, int out_size)
{
    const float* x  = (const float*)d_in[0];
    const float* wq = (const float*)d_in[1];
    const float* wk = (const float*)d_in[2];
    const float* wv = (const float*)d_in[3];
    float* out = (float*)d_out;

    const int SM3 = 2 * (2 * 3 * TILE_BYTES);   // NS=3, 2 stages: 96 KB
    const int SM2 = 3 * (2 * 2 * TILE_BYTES);   // NS=2, 3 stages: 96 KB

    static bool attr_done = false;
    if (!attr_done) {
        cudaFuncSetAttribute(mma_gemm<3, 2, bf16>, cudaFuncAttributeMaxDynamicSharedMemorySize, SM3);
        cudaFuncSetAttribute(mma_gemm<2, 3, fp16>, cudaFuncAttributeMaxDynamicSharedMemorySize, SM2);
        attr_done = true;
    }

    bf16 *x0, *x1, *x2, *wq0, *wq1, *wq2, *wk0, *wk1, *wk2;
    bf16 *q0, *q1, *q2, *k0, *k1, *k2;
    fp16 *xh0, *xh1, *wvh0, *wvh1, *v0, *v1, *vT0, *vT1, *w0, *w1;
    float* sc;
    cudaGetSymbolAddress((void**)&x0, g_x0);     cudaGetSymbolAddress((void**)&x1, g_x1);
    cudaGetSymbolAddress((void**)&x2, g_x2);
    cudaGetSymbolAddress((void**)&xh0, g_xh0);   cudaGetSymbolAddress((void**)&xh1, g_xh1);
    cudaGetSymbolAddress((void**)&wq0, g_wq0);   cudaGetSymbolAddress((void**)&wq1, g_wq1);
    cudaGetSymbolAddress((void**)&wq2, g_wq2);
    cudaGetSymbolAddress((void**)&wk0, g_wk0);   cudaGetSymbolAddress((void**)&wk1, g_wk1);
    cudaGetSymbolAddress((void**)&wk2, g_wk2);
    cudaGetSymbolAddress((void**)&wvh0, g_wvh0); cudaGetSymbolAddress((void**)&wvh1, g_wvh1);
    cudaGetSymbolAddress((void**)&q0, g_q0);     cudaGetSymbolAddress((void**)&q1, g_q1);
    cudaGetSymbolAddress((void**)&q2, g_q2);
    cudaGetSymbolAddress((void**)&k0, g_k0);     cudaGetSymbolAddress((void**)&k1, g_k1);
    cudaGetSymbolAddress((void**)&k2, g_k2);
    cudaGetSymbolAddress((void**)&v0, g_v0);     cudaGetSymbolAddress((void**)&v1, g_v1);
    cudaGetSymbolAddress((void**)&vT0, g_vT0);   cudaGetSymbolAddress((void**)&vT1, g_vT1);
    cudaGetSymbolAddress((void**)&sc, g_s);
    cudaGetSymbolAddress((void**)&w0, g_w0);     cudaGetSymbolAddress((void**)&w1, g_w1);

    // 1) splits
    split_x<<<(M_TOT * (long)D_) / (256 * 4), 256>>>(x, x0, x1, x2, xh0, xh1, (long)M_TOT * D_);
    dim3 tgrid(D_ / 32, D_ / 32);
    splitT3_f32<<<tgrid, 256>>>(wq, wq0, wq1, wq2, D_, D_);
    splitT3_f32<<<tgrid, 256>>>(wk, wk0, wk1, wk2, D_, D_);
    splitT2h_f32<<<tgrid, 256>>>(wv, wvh0, wvh1, D_, D_);

    // 2) fused Q+K projections (NS=3 bf16, 6 terms; z selects weight/output set)
    dim3 gQK(D_ / GBN, M_TOT / GBM, 2);
    mma_gemm<3, 2, bf16><<<gQK, 256, SM3>>>(x0, x1, x2,
                                   wq0, wq1, wq2, wk0, wk1, wk2,
                                   nullptr, q0, q1, q2,
                                   nullptr, k0, k1, k2,
                                   M_TOT, D_, D_, 0, 0, 0, 2, 1);
    // V projection (NS=2 fp16, 3 terms) -> 2-way fp16
    dim3 gP(D_ / GBN, M_TOT / GBM, 1);
    mma_gemm<2, 3, fp16><<<gP, 256, SM2>>>(xh0, xh1, nullptr,
                                  wvh0, wvh1, nullptr, nullptr, nullptr, nullptr,
                                  nullptr, v0, v1, nullptr,
                                  nullptr, nullptr, nullptr, nullptr,
                                  M_TOT, D_, D_, 0, 0, 0, 1, 0);

    // 3) transpose V halves: [B][S,D] -> [B][D,S]
    dim3 gT(D_ / 32, S_ / 32, B_ * 2);
    transpose_fp16<<<gT, 256>>>(v0, v1, vT0, vT1);

    // 4) scores[b] = Q[b] * K[b]^T (NS=3 bf16, 6 terms) -> fp32
    dim3 gS(S_ / GBN, S_ / GBM, B_);
    mma_gemm<3, 2, bf16><<<gS, 256, SM3>>>(q0, q1, q2,
                                  k0, k1, k2, nullptr, nullptr, nullptr,
                                  sc, nullptr, nullptr, nullptr,
                                  nullptr, nullptr, nullptr, nullptr,
                                  S_, S_, D_, (long)S_ * D_, (long)S_ * D_, (long)S_ * S_, 0, 0);

    // 5) softmax -> 2-way fp16 weights
    softmax_rows<<<B_ * S_, 256>>>(sc, w0, w1);

    // 6) out[b] = W[b] * V[b] (NS=2 fp16, 3 terms) -> fp32
    dim3 gO(D_ / GBN, S_ / GBM, B_);
    mma_gemm<2, 3, fp16><<<gO, 256, SM2>>>(w0, w1, nullptr,
                                  vT0, vT1, nullptr, nullptr, nullptr, nullptr,
                                  out, nullptr, nullptr, nullptr,
                                  nullptr, nullptr, nullptr, nullptr,
                                  S_, D_, S_, (long)S_ * S_, (long)D_ * S_, (long)S_ * D_, 0, 0);
}

// round 14
// speedup vs baseline: 1.7296x; 1.7296x over previous
#include <cuda_runtime.h>
#include <cuda_fp16.h>
#include <math.h>
#include <stdint.h>

#define B_  4
#define S_  2048
#define D_  1024
#define M_TOT (B_ * S_)   // 8192

typedef __half fp16;

// ---------------- scratch (allocation-free rule: __device__ globals) ----------------
__device__ fp16  g_x0[(size_t)M_TOT * D_], g_x1[(size_t)M_TOT * D_];
__device__ fp16  g_wq0[(size_t)D_ * D_], g_wq1[(size_t)D_ * D_];
__device__ fp16  g_wk0[(size_t)D_ * D_], g_wk1[(size_t)D_ * D_];
__device__ fp16  g_wv0[(size_t)D_ * D_], g_wv1[(size_t)D_ * D_];
__device__ fp16  g_q0[(size_t)M_TOT * D_], g_q1[(size_t)M_TOT * D_];
__device__ fp16  g_k0[(size_t)M_TOT * D_], g_k1[(size_t)M_TOT * D_];
__device__ fp16  g_v0[(size_t)M_TOT * D_], g_v1[(size_t)M_TOT * D_];
__device__ fp16  g_vT0[(size_t)M_TOT * D_], g_vT1[(size_t)M_TOT * D_];   // [B][D,S]
__device__ float g_s[(size_t)B_ * S_ * S_];                              // scores fp32
__device__ fp16  g_w0[(size_t)B_ * S_ * S_], g_w1[(size_t)B_ * S_ * S_]; // weights split

// ---------------- helpers ----------------
__device__ __forceinline__ uint32_t smem_u32(const void* p) {
    uint32_t a;
    asm("{ .reg .u64 t; cvta.to.shared.u64 t, %1; cvt.u32.u64 %0, t; }" : "=r"(a) : "l"(p));
    return a;
}
__device__ __forceinline__ void cp_async16(uint32_t dst, const void* src) {
    asm volatile("cp.async.cg.shared.global [%0], [%1], 16;" :: "r"(dst), "l"(src) : "memory");
}
__device__ __forceinline__ void cp_commit() { asm volatile("cp.async.commit_group;" ::: "memory"); }
__device__ __forceinline__ void cp_wait0()  { asm volatile("cp.async.wait_group 0;"  ::: "memory"); }

__device__ __forceinline__ void ldsm_x4(uint32_t* r, uint32_t addr) {
    asm volatile("ldmatrix.sync.aligned.m8n8.x4.shared.b16 {%0,%1,%2,%3}, [%4];"
        : "=r"(r[0]), "=r"(r[1]), "=r"(r[2]), "=r"(r[3]) : "r"(addr));
}
__device__ __forceinline__ void ldsm_x2(uint32_t* r, uint32_t addr) {
    asm volatile("ldmatrix.sync.aligned.m8n8.x2.shared.b16 {%0,%1}, [%2];"
        : "=r"(r[0]), "=r"(r[1]) : "r"(addr));
}
__device__ __forceinline__ void mma_h(float* c, const uint32_t* a, const uint32_t* b) {
    asm volatile(
        "mma.sync.aligned.m16n8k16.row.col.f32.f16.f16.f32 "
        "{%0,%1,%2,%3}, {%4,%5,%6,%7}, {%8,%9}, {%0,%1,%2,%3};"
        : "+f"(c[0]), "+f"(c[1]), "+f"(c[2]), "+f"(c[3])
        : "r"(a[0]), "r"(a[1]), "r"(a[2]), "r"(a[3]), "r"(b[0]), "r"(b[1]));
}
__device__ __forceinline__ uint32_t pack2h(fp16 a, fp16 b) {
    uint32_t u; fp16* p = (fp16*)&u; p[0] = a; p[1] = b; return u;
}

// Swizzled tile: 128 logical rows x 64 B (one GBK=32 K-slice of fp16).
// Rows packed pairwise into 64 storage rows of 128 B, then SW128 XOR.
#define SWZ128(x) ((x) ^ (((x) >> 3) & 0x70))
__device__ __forceinline__ uint32_t tile_off(uint32_t row, uint32_t colb) {
    return SWZ128(((row & 63u) << 7) + ((row >> 6) << 6) + colb);
}

// ---------------- GEMM: C[M,N] = (A0+A1)[M,K] * (B0+B1)[N,K]^T, 3-term split ----
// mode 0: fp32 C ; mode 1: 2-way fp16 (C0,C1)
// zmode 0: blockIdx.z = batch (strides sA/sB/sC)
// zmode 1: blockIdx.z in {0,1,2} selects B/C set a/b/c  [QKV fusion]
#define GBM 128
#define GBN 128
#define GBK 32
#define TILE_BYTES 8192
#define STAGE_BYTES (4 * TILE_BYTES)   // A0,A1,B0,B1 = 32 KB
#define SMEM_GEMM (2 * STAGE_BYTES)    // 64 KB

__global__ __launch_bounds__(256, 2) void mma_gemm_h(
    const fp16* __restrict__ A0, const fp16* __restrict__ A1,
    const fp16* Ba0, const fp16* Ba1, const fp16* Bb0, const fp16* Bb1,
    const fp16* Bc0, const fp16* Bc1,
    float* C, fp16* Ca0, fp16* Ca1, fp16* Cb0, fp16* Cb1, fp16* Cc0, fp16* Cc1,
    int M, int N, int K, long sA, long sB, long sC, int mode, int zmode)
{
    extern __shared__ char sm[];
    const uint32_t sbase = smem_u32(sm);

    const int tid  = threadIdx.x;
    const int wid  = tid >> 5;
    const int lane = tid & 31;
    const int gid  = lane >> 2;
    const int tig  = lane & 3;

    const fp16* B0 = Ba0; const fp16* B1 = Ba1;
    fp16* C0 = Ca0; fp16* C1 = Ca1;
    if (zmode == 1) {
        if (blockIdx.z == 1)      { B0 = Bb0; B1 = Bb1; C0 = Cb0; C1 = Cb1; }
        else if (blockIdx.z == 2) { B0 = Bc0; B1 = Bc1; C0 = Cc0; C1 = Cc1; }
    }
    const long zb = (zmode == 0) ? (long)blockIdx.z : 0;

    const int by = blockIdx.y * GBM;
    const int bx = blockIdx.x * GBN;

    const fp16* srcs[4];
    srcs[0] = A0 + zb * sA + (long)by * K;
    srcs[1] = A1 + zb * sA + (long)by * K;
    srcs[2] = B0 + zb * sB + (long)bx * K;
    srcs[3] = B1 + zb * sB + (long)bx * K;

    const int NT = K / GBK;

    auto load_stage = [&](int st, int kt) {
        #pragma unroll
        for (int t = 0; t < 4; t++) {
            const char* sp = (const char*)srcs[t] + kt * 64;
            uint32_t db = sbase + st * STAGE_BYTES + t * TILE_BYTES;
            #pragma unroll
            for (int p = 0; p < 2; p++) {
                int idx = p * 256 + tid;       // 0..511
                uint32_t row = idx >> 2;
                uint32_t c   = idx & 3;
                cp_async16(db + tile_off(row, c << 4), sp + (long)row * K * 2 + c * 16);
            }
        }
        cp_commit();
    };

    const int wm = (wid & 1) * 64;
    const int wn = (wid >> 1) * 32;

    float acc[4][4][4] = {};

    load_stage(0, 0);

    for (int kt = 0; kt < NT; kt++) {
        cp_wait0();
        __syncthreads();
        if (kt + 1 < NT) load_stage((kt + 1) & 1, kt + 1);

        uint32_t abase = sbase + (kt & 1) * STAGE_BYTES;
        #pragma unroll
        for (int ks = 0; ks < GBK; ks += 16) {
            // B fragments upfront (2 splits x 4 nt = 8 ldsm_x2)
            uint32_t b[2][4][2];
            #pragma unroll
            for (int nt = 0; nt < 4; nt++) {
                uint32_t r = wn + nt * 8 + (lane & 7);
                uint32_t cb = ((ks >> 3) + ((lane >> 3) & 1)) << 4;
                uint32_t rb = abase + 2 * TILE_BYTES + tile_off(r, cb);
                #pragma unroll
                for (int s = 0; s < 2; s++)
                    ldsm_x2(b[s][nt], rb + s * TILE_BYTES);
            }
            // A per mt, then MMAs
            #pragma unroll
            for (int mt = 0; mt < 4; mt++) {
                uint32_t a[2][4];
                uint32_t r = wm + mt * 16 + (lane & 15);
                uint32_t cb = ((ks >> 3) + (lane >> 4)) << 4;
                uint32_t ra = abase + tile_off(r, cb);
                #pragma unroll
                for (int s = 0; s < 2; s++)
                    ldsm_x4(a[s], ra + s * TILE_BYTES);
                #pragma unroll
                for (int nt = 0; nt < 4; nt++) {
                    mma_h(acc[mt][nt], a[0], b[0][nt]);
                    mma_h(acc[mt][nt], a[0], b[1][nt]);
                    mma_h(acc[mt][nt], a[1], b[0][nt]);
                }
            }
        }
        __syncthreads();
    }

    // epilogue
    #pragma unroll
    for (int mt = 0; mt < 4; mt++) {
        #pragma unroll
        for (int nt = 0; nt < 4; nt++) {
            int col = bx + wn + nt * 8 + 2 * tig;
            #pragma unroll
            for (int h = 0; h < 2; h++) {
                int row = by + wm + mt * 16 + gid + h * 8;
                float v0 = acc[mt][nt][2 * h + 0];
                float v1 = acc[mt][nt][2 * h + 1];
                if (mode == 0) {
                    *(float2*)(C + zb * sC + (long)row * N + col) = make_float2(v0, v1);
                } else {
                    long base = (long)row * N + col;
                    fp16 h0 = __float2half_rn(v0);
                    fp16 h1 = __float2half_rn(v1);
                    fp16 l0 = __float2half_rn(v0 - __half2float(h0));
                    fp16 l1 = __float2half_rn(v1 - __half2float(h1));
                    *(uint32_t*)(C0 + base) = pack2h(h0, h1);
                    *(uint32_t*)(C1 + base) = pack2h(l0, l1);
                }
            }
        }
    }
}

// ---------------- split x: fp32 -> 2-way fp16 ----------------
__global__ __launch_bounds__(256) void split_x(const float* __restrict__ in,
        fp16* __restrict__ p0, fp16* __restrict__ p1, long n)
{
    long i = ((long)blockIdx.x * 256 + threadIdx.x) * 4;
    if (i >= n) return;
    float4 v = *(const float4*)(in + i);
    float vv[4] = {v.x, v.y, v.z, v.w};
    fp16 h[4], l[4];
    #pragma unroll
    for (int j = 0; j < 4; j++) {
        h[j] = __float2half_rn(vv[j]);
        l[j] = __float2half_rn(vv[j] - __half2float(h[j]));
    }
    *(uint32_t*)(p0 + i) = pack2h(h[0], h[1]); *(uint32_t*)(p0 + i + 2) = pack2h(h[2], h[3]);
    *(uint32_t*)(p1 + i) = pack2h(l[0], l[1]); *(uint32_t*)(p1 + i + 2) = pack2h(l[2], l[3]);
}

// ---------------- split + transpose: fp32 [K,N] -> 2-way fp16 [N,K] ----------------
__global__ __launch_bounds__(256) void splitT2h_f32(const float* __restrict__ in,
        fp16* __restrict__ o0, fp16* __restrict__ o1, int Kd, int Nd)
{
    __shared__ float t[32][33];
    int tx = threadIdx.x & 31, ty = threadIdx.x >> 5;
    int c0 = blockIdx.x * 32, r0 = blockIdx.y * 32;
    #pragma unroll
    for (int j = 0; j < 4; j++)
        t[ty + j * 8][tx] = in[(long)(r0 + ty + j * 8) * Nd + c0 + tx];
    __syncthreads();
    #pragma unroll
    for (int j = 0; j < 4; j++) {
        float v = t[tx][ty + j * 8];
        fp16 h = __float2half_rn(v);
        fp16 l = __float2half_rn(v - __half2float(h));
        long o = (long)(c0 + ty + j * 8) * Kd + r0 + tx;
        o0[o] = h; o1[o] = l;
    }
}

// ---------------- batched fp16 transpose: [B][S,D] -> [B][D,S]  (z = batch*2 + which) --
__global__ __launch_bounds__(256) void transpose_fp16(const fp16* __restrict__ inh, const fp16* __restrict__ inl,
                                                      fp16* __restrict__ outh, fp16* __restrict__ outl)
{
    __shared__ fp16 t[32][33];
    int which = blockIdx.z & 1, b = blockIdx.z >> 1;
    const fp16* in = which ? inl : inh;
    fp16* out = which ? outl : outh;
    in  += (long)b * S_ * D_;
    out += (long)b * S_ * D_;
    int tx = threadIdx.x & 31, ty = threadIdx.x >> 5;
    int c0 = blockIdx.x * 32, r0 = blockIdx.y * 32;
    #pragma unroll
    for (int j = 0; j < 4; j++)
        t[ty + j * 8][tx] = in[(long)(r0 + ty + j * 8) * D_ + c0 + tx];
    __syncthreads();
    #pragma unroll
    for (int j = 0; j < 4; j++)
        out[(long)(c0 + ty + j * 8) * S_ + r0 + tx] = t[tx][ty + j * 8];
}

// ---------------- softmax: fp32 scores row -> 2-way fp16 weights ----------------
__global__ __launch_bounds__(256) void softmax_rows(const float* __restrict__ Sp,
                                                    fp16* __restrict__ W0, fp16* __restrict__ W1)
{
    const float* p = Sp + (long)blockIdx.x * S_;
    fp16* p0 = W0 + (long)blockIdx.x * S_;
    fp16* p1 = W1 + (long)blockIdx.x * S_;
    const int tid = threadIdx.x;
    const int PER = S_ / 256;

    float vals[PER];
    float lmax = -INFINITY;
    #pragma unroll
    for (int i = 0; i < PER; i++) {
        vals[i] = p[tid + i * 256];
        lmax = fmaxf(lmax, vals[i]);
    }
    __shared__ float red[8];
    #pragma unroll
    for (int o = 16; o; o >>= 1) lmax = fmaxf(lmax, __shfl_xor_sync(0xFFFFFFFFu, lmax, o));
    if ((tid & 31) == 0) red[tid >> 5] = lmax;
    __syncthreads();
    float m = red[0];
    #pragma unroll
    for (int w = 1; w < 8; w++) m = fmaxf(m, red[w]);
    __syncthreads();

    float lsum = 0.f;
    #pragma unroll
    for (int i = 0; i < PER; i++) { vals[i] = expf(vals[i] - m); lsum += vals[i]; }
    #pragma unroll
    for (int o = 16; o; o >>= 1) lsum += __shfl_xor_sync(0xFFFFFFFFu, lsum, o);
    if ((tid & 31) == 0) red[tid >> 5] = lsum;
    __syncthreads();
    float s = 0.f;
    #pragma unroll
    for (int w = 0; w < 8; w++) s += red[w];
    float inv = 1.0f / s;
    #pragma unroll
    for (int i = 0; i < PER; i++) {
        float w = vals[i] * inv;
        fp16 h = __float2half_rn(w);
        fp16 l = __float2half_rn(w - __half2float(h));
        p0[tid + i * 256] = h;
        p1[tid + i * 256] = l;
    }
}

// ---------------- launch ----------------
extern "C" void kernel_launch(void* const* d_in, const int* in_sizes, int n_in,
                              void* d_out, int out_size)
{
    const float* x  = (const float*)d_in[0];
    const float* wq = (const float*)d_in[1];
    const float* wk = (const float*)d_in[2];
    const float* wv = (const float*)d_in[3];
    float* out = (float*)d_out;

    static bool attr_done = false;
    if (!attr_done) {
        cudaFuncSetAttribute(mma_gemm_h, cudaFuncAttributeMaxDynamicSharedMemorySize, SMEM_GEMM);
        attr_done = true;
    }

    fp16 *x0, *x1, *wq0, *wq1, *wk0, *wk1, *wv0, *wv1;
    fp16 *q0, *q1, *k0, *k1, *v0, *v1, *vT0, *vT1, *w0, *w1;
    float* sc;
    cudaGetSymbolAddress((void**)&x0, g_x0);     cudaGetSymbolAddress((void**)&x1, g_x1);
    cudaGetSymbolAddress((void**)&wq0, g_wq0);   cudaGetSymbolAddress((void**)&wq1, g_wq1);
    cudaGetSymbolAddress((void**)&wk0, g_wk0);   cudaGetSymbolAddress((void**)&wk1, g_wk1);
    cudaGetSymbolAddress((void**)&wv0, g_wv0);   cudaGetSymbolAddress((void**)&wv1, g_wv1);
    cudaGetSymbolAddress((void**)&q0, g_q0);     cudaGetSymbolAddress((void**)&q1, g_q1);
    cudaGetSymbolAddress((void**)&k0, g_k0);     cudaGetSymbolAddress((void**)&k1, g_k1);
    cudaGetSymbolAddress((void**)&v0, g_v0);     cudaGetSymbolAddress((void**)&v1, g_v1);
    cudaGetSymbolAddress((void**)&vT0, g_vT0);   cudaGetSymbolAddress((void**)&vT1, g_vT1);
    cudaGetSymbolAddress((void**)&sc, g_s);
    cudaGetSymbolAddress((void**)&w0, g_w0);     cudaGetSymbolAddress((void**)&w1, g_w1);

    // 1) splits
    split_x<<<(M_TOT * (long)D_) / (256 * 4), 256>>>(x, x0, x1, (long)M_TOT * D_);
    dim3 tgrid(D_ / 32, D_ / 32);
    splitT2h_f32<<<tgrid, 256>>>(wq, wq0, wq1, D_, D_);
    splitT2h_f32<<<tgrid, 256>>>(wk, wk0, wk1, D_, D_);
    splitT2h_f32<<<tgrid, 256>>>(wv, wv0, wv1, D_, D_);

    // 2) fused Q+K+V projections (z selects weight/output set) -> 2-way fp16
    dim3 gQKV(D_ / GBN, M_TOT / GBM, 3);
    mma_gemm_h<<<gQKV, 256, SMEM_GEMM>>>(x0, x1,
                                         wq0, wq1, wk0, wk1, wv0, wv1,
                                         nullptr, q0, q1, k0, k1, v0, v1,
                                         M_TOT, D_, D_, 0, 0, 0, 1, 1);

    // 3) transpose V halves: [B][S,D] -> [B][D,S]
    dim3 gT(D_ / 32, S_ / 32, B_ * 2);
    transpose_fp16<<<gT, 256>>>(v0, v1, vT0, vT1);

    // 4) scores[b] = Q[b] * K[b]^T -> fp32
    dim3 gS(S_ / GBN, S_ / GBM, B_);
    mma_gemm_h<<<gS, 256, SMEM_GEMM>>>(q0, q1,
                                       k0, k1, nullptr, nullptr, nullptr, nullptr,
                                       sc, nullptr, nullptr, nullptr, nullptr, nullptr, nullptr,
                                       S_, S_, D_, (long)S_ * D_, (long)S_ * D_, (long)S_ * S_, 0, 0);

    // 5) softmax -> 2-way fp16 weights
    softmax_rows<<<B_ * S_, 256>>>(sc, w0, w1);

    // 6) out[b] = W[b] * V[b] -> fp32
    dim3 gO(D_ / GBN, S_ / GBM, B_);
    mma_gemm_h<<<gO, 256, SMEM_GEMM>>>(w0, w1,
                                       vT0, vT1, nullptr, nullptr, nullptr, nullptr,
                                       out, nullptr, nullptr, nullptr, nullptr, nullptr, nullptr,
                                       S_, D_, S_, (long)S_ * S_, (long)D_ * S_, (long)S_ * D_, 0, 0);
}